// round 8
// baseline (speedup 1.0000x reference)
#include <cuda_runtime.h>
#include <math.h>
#include <stdint.h>

// Problem constants
#define NN 4096
#define NU_ 100000
#define NR_ 32
#define NA_ 5000

// ---------------- device global scratch (allocation-free) ----------------
__device__ float g_Tu[(size_t)NU_ * 256];   // u2e @ W1[256:384]
__device__ float g_Ta[(size_t)NA_ * 256];   // ua2e @ W1[384:512]
__device__ float g_Tr1[NR_ * 256];          // r2e @ W1[0:128]
__device__ float g_Tr2[NR_ * 256];          // r2e @ W1[128:256]
__device__ float g_se[NN * 128];            // u2e[nodes] @ A1[128:256] + ab1
// Weight fragments for mma.sync m16n8k16 bf16: RAW fp32 quads per (k16,nt,lane):
// {B[k0][n], B[k0+1][n], B[k0+8][n], B[k0+9][n]}, k0 = ks*16 + 2*(lane&3),
// n = nt*8 + (lane>>2). bf16 hi/lo split happens in registers at consume time.
__device__ float4 g_W2f[16 * 16 * 32];      // W2 [256x128]: [ks16][nt16][lane]
__device__ float4 g_A1f[8 * 16 * 32];       // A1[0:128][128]
__device__ float4 g_A2f[8 * 16 * 32];       // A2 [128x128]
__device__ float4 g_W1f[4 * 8 * 32 * 32];   // W1 [512x256]: [p][ks16][nt32][lane]

// ---------------- helpers ----------------
// pack two fp32 -> bf16x2 reg {lo=lo_src, hi=hi_src}
__device__ __forceinline__ uint32_t bf2(float hi, float lo) {
    uint32_t d;
    asm("cvt.rn.satfinite.bf16x2.f32 %0, %1, %2;" : "=r"(d) : "f"(hi), "f"(lo));
    return d;
}
// residual pair: (x - bf16(x)) for both halves, packed bf16x2
__device__ __forceinline__ uint32_t bf2_res(float lo, float hi, uint32_t h) {
    const float h0 = __uint_as_float(h << 16);
    const float h1 = __uint_as_float(h & 0xffff0000u);
    return bf2(hi - h1, lo - h0);
}
__device__ __forceinline__ void hmma(float c[4],
    uint32_t a0, uint32_t a1, uint32_t a2, uint32_t a3,
    uint32_t b0, uint32_t b1)
{
    asm volatile(
        "mma.sync.aligned.m16n8k16.row.col.f32.bf16.bf16.f32 "
        "{%0,%1,%2,%3}, {%4,%5,%6,%7}, {%8,%9}, {%0,%1,%2,%3};"
        : "+f"(c[0]), "+f"(c[1]), "+f"(c[2]), "+f"(c[3])
        : "r"(a0), "r"(a1), "r"(a2), "r"(a3), "r"(b0), "r"(b1));
}

// Warp-level 16x(NT*8) GEMM, bf16 2-way split, 3 products (~17-bit mantissa).
// ksteps = K/16. A fp32 in smem (row-major, astride), B raw-fp32 frags in gmem.
template<int NT>
__device__ __forceinline__ void warp_gemm_bf(
    const float* __restrict__ As, int astride, int ksteps,
    const float4* __restrict__ Bf, int ntot, int nt_base,
    int gid, int tid4, int lane, float acc[NT][4])
{
    #pragma unroll
    for (int i = 0; i < NT; i++)
        #pragma unroll
        for (int c = 0; c < 4; c++) acc[i][c] = 0.f;

    for (int ks = 0; ks < ksteps; ks++) {
        const float* ra = As + gid * astride + ks * 16 + 2 * tid4;
        const float* rb = As + (gid + 8) * astride + ks * 16 + 2 * tid4;
        const float2 xa = *(const float2*)(ra);        // a0: row gid,   k 2t4..+1
        const float2 xb = *(const float2*)(ra + 8);    // a2: row gid,   k +8
        const float2 xc = *(const float2*)(rb);        // a1: row gid+8, k 2t4..+1
        const float2 xd = *(const float2*)(rb + 8);    // a3: row gid+8, k +8
        const uint32_t ah0 = bf2(xa.y, xa.x), al0 = bf2_res(xa.x, xa.y, ah0);
        const uint32_t ah1 = bf2(xc.y, xc.x), al1 = bf2_res(xc.x, xc.y, ah1);
        const uint32_t ah2 = bf2(xb.y, xb.x), al2 = bf2_res(xb.x, xb.y, ah2);
        const uint32_t ah3 = bf2(xd.y, xd.x), al3 = bf2_res(xd.x, xd.y, ah3);
        const float4* bp = Bf + (ks * ntot + nt_base) * 32 + lane;
        #pragma unroll
        for (int nt = 0; nt < NT; nt++) {
            const float4 b = __ldg(bp + nt * 32);
            const uint32_t bh0 = bf2(b.y, b.x), bl0 = bf2_res(b.x, b.y, bh0);
            const uint32_t bh1 = bf2(b.w, b.z), bl1 = bf2_res(b.z, b.w, bh1);
            hmma(acc[nt], ah0, ah1, ah2, ah3, bh0, bh1);
            hmma(acc[nt], ah0, ah1, ah2, ah3, bl0, bl1);
            hmma(acc[nt], al0, al1, al2, al3, bh0, bh1);
        }
    }
}

// ---------------- SMEM layout for agg (float indices), 1 node/CTA ----------------
#define OFF_B1   0      // 256
#define OFF_B2   256    // 128
#define OFF_SE   384    // 128
#define OFF_AB2  512    // 128
#define OFF_A3   640    // 128
#define OFF_LGP  768    // 128
#define OFF_LG   896    // 64
#define OFF_REL  960    // 128 ints
#define OFF_NBR  1088   // 64 ints
#define OFF_ATT  1152   // 512 ints
#define OFF_H1   1664   // 64 x 260
#define OFF_H    18304  // 64 x 132
#define H1S      260
#define HS       132
#define SMEM_FLOATS 26752
#define SMEM_BYTES  (SMEM_FLOATS * 4)   // 107008

// ---------------- Fragment builders (raw fp32, pure transpose) ----------------
__global__ __launch_bounds__(256) void frag_kernel(
    const float* __restrict__ W2, const float* __restrict__ A1,
    const float* __restrict__ A2)
{
    int idx = blockIdx.x * 256 + threadIdx.x;   // 16384 total
    const float* W;
    float4* out;
    int j;
    if (idx < 8192)       { W = W2; out = g_W2f; j = idx; }
    else if (idx < 12288) { W = A1; out = g_A1f; j = idx - 8192; }
    else if (idx < 16384) { W = A2; out = g_A2f; j = idx - 12288; }
    else return;
    const int ks = j >> 9;              // 16 nt x 32 lane = 512 per ks
    const int nt = (j >> 5) & 15;
    const int lane = j & 31;
    const int k0 = ks * 16 + 2 * (lane & 3);
    const int n = nt * 8 + (lane >> 2);
    float4 o;
    o.x = W[(k0    ) * 128 + n];
    o.y = W[(k0 + 1) * 128 + n];
    o.z = W[(k0 + 8) * 128 + n];
    o.w = W[(k0 + 9) * 128 + n];
    out[j] = o;
}

// W1 [512][256] row-major -> 4 parts of [128][256], ntot=32.
__global__ __launch_bounds__(256) void frag_w1_kernel(const float* __restrict__ W1)
{
    int idx = blockIdx.x * 256 + threadIdx.x;   // 32768 total
    if (idx >= 32768) return;
    const int p = idx >> 13;            // 8192 per part
    const int j = idx & 8191;
    const int ks = j >> 10;             // 32 nt x 32 lane = 1024 per ks
    const int nt = (j >> 5) & 31;
    const int lane = j & 31;
    const int k0 = ks * 16 + 2 * (lane & 3);
    const int n = nt * 8 + (lane >> 2);
    const int r = p * 128 + k0;
    float4 o;
    o.x = W1[(r    ) * 256 + n];
    o.y = W1[(r + 1) * 256 + n];
    o.z = W1[(r + 8) * 256 + n];
    o.w = W1[(r + 9) * 256 + n];
    g_W1f[p * 8192 + j] = o;
}

// ---------------- se precompute ----------------
__global__ __launch_bounds__(128) void se_kernel(
    const int* __restrict__ nodes, const float* __restrict__ u2e,
    const float* __restrict__ A1, const float* __restrict__ ab1)
{
    const int n = blockIdx.x;
    const int d = threadIdx.x;
    __shared__ float s[128];
    s[d] = u2e[(size_t)nodes[n] * 128 + d];
    __syncthreads();
    float acc = ab1[d];
    #pragma unroll 4
    for (int i = 0; i < 128; i++) acc = fmaf(s[i], A1[(128 + i) * 128 + d], acc);
    g_se[n * 128 + d] = acc;
}

// ---------------- Unified tensor-core table kernel: 64 rows/CTA (proven shape) ----------------
#define TU_CTAS 1563
#define TA_CTAS 79
__global__ __launch_bounds__(256) void mma_table_kernel(
    const float* __restrict__ u2e, const float* __restrict__ ua2e,
    const float* __restrict__ r2e)
{
    __shared__ float s_a[64 * 132];
    const int b = blockIdx.x;
    const int t = threadIdx.x;

    const float* emb; float* out; const float4* Bf; int rows; int row0;
    if (b < TU_CTAS)                 { emb = u2e;  out = g_Tu;  Bf = g_W1f + 2 * 8192; rows = NU_; row0 = b * 64; }
    else if (b < TU_CTAS + TA_CTAS)  { emb = ua2e; out = g_Ta;  Bf = g_W1f + 3 * 8192; rows = NA_; row0 = (b - TU_CTAS) * 64; }
    else if (b == TU_CTAS + TA_CTAS) { emb = r2e;  out = g_Tr1; Bf = g_W1f;            rows = NR_; row0 = 0; }
    else                             { emb = r2e;  out = g_Tr2; Bf = g_W1f + 1 * 8192; rows = NR_; row0 = 0; }

    for (int i = t; i < 64 * 32; i += 256) {
        const int r = i >> 5, c4 = i & 31;
        float4 v = make_float4(0.f, 0.f, 0.f, 0.f);
        if (row0 + r < rows)
            v = *(const float4*)(emb + (size_t)(row0 + r) * 128 + c4 * 4);
        *(float4*)(s_a + r * 132 + c4 * 4) = v;
    }
    __syncthreads();

    const int w = t >> 5, lane = t & 31;
    const int gid = lane >> 2, tid4 = lane & 3;
    const int rt = w & 3;              // 4 row tiles of 16
    const int ch = w >> 2;             // 2 column halves (16 nt each)
    const int nt_base = ch * 16;

    float acc[16][4];
    warp_gemm_bf<16>(s_a + rt * 16 * 132, 132, 8, Bf, 32, nt_base,
                     gid, tid4, lane, acc);

    const int r0 = rt * 16 + gid;
    #pragma unroll
    for (int nt = 0; nt < 16; nt++) {
        const int col = (nt_base + nt) * 8 + 2 * tid4;
        if (row0 + r0 < rows) {
            float2 v; v.x = acc[nt][0]; v.y = acc[nt][1];
            *(float2*)(out + (size_t)(row0 + r0) * 256 + col) = v;
        }
        if (row0 + r0 + 8 < rows) {
            float2 v; v.x = acc[nt][2]; v.y = acc[nt][3];
            *(float2*)(out + (size_t)(row0 + r0 + 8) * 256 + col) = v;
        }
    }
}

// ---------------- agg epilogue helper ----------------
__device__ __forceinline__ void warp_epilogue(
    const float acc[8][4], const float* __restrict__ bias,
    float* __restrict__ dst, int dstride, int rt, int nt_base, int gid, int tid4)
{
    const int row0 = rt * 16 + gid;
    #pragma unroll
    for (int nt = 0; nt < 8; nt++) {
        const int col = (nt_base + nt) * 8 + 2 * tid4;
        const float b0 = bias[col], b1 = bias[col + 1];
        float2 v0, v1;
        v0.x = fmaxf(acc[nt][0] + b0, 0.f);
        v0.y = fmaxf(acc[nt][1] + b1, 0.f);
        v1.x = fmaxf(acc[nt][2] + b0, 0.f);
        v1.y = fmaxf(acc[nt][3] + b1, 0.f);
        *(float2*)(dst + row0 * dstride + col) = v0;
        *(float2*)(dst + (row0 + 8) * dstride + col) = v1;
    }
}

// ---------------- Fused kernel: one CTA = one node (64 paths), 256 thr ----------------
__global__ __launch_bounds__(256, 2) void agg_mma_kernel(
    const int* __restrict__ prel, const int* __restrict__ pnbr,
    const int* __restrict__ attrs,
    const float* __restrict__ b1, const float* __restrict__ b2,
    const float* __restrict__ ab2, const float* __restrict__ A3,
    const float* __restrict__ ab3, float* __restrict__ out)
{
    extern __shared__ float sm[];
    const int n = blockIdx.x;
    const int t = threadIdx.x;
    const int w = t >> 5, lane = t & 31;
    const int gid = lane >> 2, tid4 = lane & 3;
    const int rt = w & 3;
    const int ch = w >> 2;
    const int nt_base = ch * 8;

    int* s_rel = (int*)(sm + OFF_REL);
    int* s_nbr = (int*)(sm + OFF_NBR);
    int* s_att = (int*)(sm + OFF_ATT);

    sm[OFF_B1 + t] = b1[t];
    if (t < 128) {
        sm[OFF_B2 + t] = b2[t];
        sm[OFF_SE + t] = g_se[n * 128 + t];
        sm[OFF_AB2 + t] = ab2[t];
        sm[OFF_A3 + t] = A3[t];
        s_rel[t] = prel[n * 128 + t];
    }
    if (t < 64) s_nbr[t] = pnbr[n * 64 + t];
    for (int i = t; i < 512; i += 256) s_att[i] = attrs[n * 512 + i];
    __syncthreads();

    // ---- gather: h1[k][0:256] = relu(b1 + Tr1 + Tr2 + Tu + sum_a Ta) ----
    {
        float* s_h1 = sm + OFF_H1;
        const int ks = t >> 6;
        const int jj = t & 63;
        for (int kb = 0; kb < 16; kb++) {
            const int k = kb * 4 + ks;
            const int r0 = s_rel[2 * k], r1 = s_rel[2 * k + 1], nb = s_nbr[k];
            float4 acc = *(const float4*)(sm + OFF_B1 + jj * 4);
            float4 v;
            v = ((const float4*)(g_Tr1 + r0 * 256))[jj];
            acc.x += v.x; acc.y += v.y; acc.z += v.z; acc.w += v.w;
            v = ((const float4*)(g_Tr2 + r1 * 256))[jj];
            acc.x += v.x; acc.y += v.y; acc.z += v.z; acc.w += v.w;
            v = ((const float4*)(g_Tu + (size_t)nb * 256))[jj];
            acc.x += v.x; acc.y += v.y; acc.z += v.z; acc.w += v.w;
            #pragma unroll
            for (int a = 0; a < 8; a++) {
                v = ((const float4*)(g_Ta + (size_t)s_att[k * 8 + a] * 256))[jj];
                acc.x += v.x; acc.y += v.y; acc.z += v.z; acc.w += v.w;
            }
            acc.x = fmaxf(acc.x, 0.f); acc.y = fmaxf(acc.y, 0.f);
            acc.z = fmaxf(acc.z, 0.f); acc.w = fmaxf(acc.w, 0.f);
            ((float4*)(s_h1 + k * H1S))[jj] = acc;
        }
    }
    __syncthreads();

    float acc[8][4];

    // ---- GEMM1: h = relu(h1 @ W2 + b2)   K=256 ----
    warp_gemm_bf<8>(sm + OFF_H1 + rt * 16 * H1S, H1S, 16, g_W2f, 16, nt_base,
                    gid, tid4, lane, acc);
    warp_epilogue(acc, sm + OFF_B2, sm + OFF_H, HS, rt, nt_base, gid, tid4);
    __syncthreads();

    // ---- GEMM2: a1 = relu(h @ A1[0:128] + se)   K=128 ----
    warp_gemm_bf<8>(sm + OFF_H + rt * 16 * HS, HS, 8, g_A1f, 16, nt_base,
                    gid, tid4, lane, acc);
    warp_epilogue(acc, sm + OFF_SE, sm + OFF_H1, HS, rt, nt_base, gid, tid4);
    __syncthreads();

    // ---- GEMM3: a2 = relu(a1 @ A2 + ab2); logits fused   K=128 ----
    warp_gemm_bf<8>(sm + OFF_H1 + rt * 16 * HS, HS, 8, g_A2f, 16, nt_base,
                    gid, tid4, lane, acc);
    {
        float p0 = 0.f, p1 = 0.f;
        #pragma unroll
        for (int nt = 0; nt < 8; nt++) {
            const int col = (nt_base + nt) * 8 + 2 * tid4;
            const float b0 = sm[OFF_AB2 + col], b1v = sm[OFF_AB2 + col + 1];
            const float w0 = sm[OFF_A3 + col], w1 = sm[OFF_A3 + col + 1];
            p0 = fmaf(fmaxf(acc[nt][0] + b0, 0.f), w0, p0);
            p0 = fmaf(fmaxf(acc[nt][1] + b1v, 0.f), w1, p0);
            p1 = fmaf(fmaxf(acc[nt][2] + b0, 0.f), w0, p1);
            p1 = fmaf(fmaxf(acc[nt][3] + b1v, 0.f), w1, p1);
        }
        p0 += __shfl_xor_sync(0xffffffffu, p0, 1);
        p0 += __shfl_xor_sync(0xffffffffu, p0, 2);
        p1 += __shfl_xor_sync(0xffffffffu, p1, 1);
        p1 += __shfl_xor_sync(0xffffffffu, p1, 2);
        if (tid4 == 0) {
            sm[OFF_LGP + ch * 64 + rt * 16 + gid] = p0;
            sm[OFF_LGP + ch * 64 + rt * 16 + gid + 8] = p1;
        }
    }
    __syncthreads();

    // ---- softmax over 64 logits (warp 0) ----
    if (t < 32) {
        const float a3b = ab3[0];
        float l0 = a3b + sm[OFF_LGP + t] + sm[OFF_LGP + 64 + t];
        float l1 = a3b + sm[OFF_LGP + t + 32] + sm[OFF_LGP + 96 + t];
        float m = fmaxf(l0, l1);
        #pragma unroll
        for (int off = 16; off; off >>= 1)
            m = fmaxf(m, __shfl_xor_sync(0xffffffffu, m, off));
        float e0 = expf(l0 - m), e1 = expf(l1 - m);
        float s = e0 + e1;
        #pragma unroll
        for (int off = 16; off; off >>= 1)
            s += __shfl_xor_sync(0xffffffffu, s, off);
        const float inv = 1.f / s;
        sm[OFF_LG + t] = e0 * inv;
        sm[OFF_LG + t + 32] = e1 * inv;
    }
    __syncthreads();

    // ---- out[n][d] = sum_k w[k] * h[k][d] ----
    if (t < 128) {
        const float* hb = sm + OFF_H;
        float acc2 = 0.f;
        #pragma unroll 4
        for (int k = 0; k < 64; k++)
            acc2 = fmaf(sm[OFF_LG + k], hb[k * HS + t], acc2);
        out[(size_t)n * 128 + t] = acc2;
    }
}

// -------------------------------------------------------------------------
extern "C" void kernel_launch(void* const* d_in, const int* in_sizes, int n_in,
                              void* d_out, int out_size)
{
    const int*   nodes = (const int*)d_in[0];
    const int*   prel  = (const int*)d_in[1];
    const int*   pnbr  = (const int*)d_in[2];
    const int*   attrs = (const int*)d_in[3];
    const float* u2e   = (const float*)d_in[4];
    const float* r2e   = (const float*)d_in[5];
    const float* ua2e  = (const float*)d_in[6];
    const float* W1    = (const float*)d_in[7];
    const float* b1    = (const float*)d_in[8];
    const float* W2    = (const float*)d_in[9];
    const float* b2    = (const float*)d_in[10];
    const float* A1    = (const float*)d_in[11];
    const float* ab1   = (const float*)d_in[12];
    const float* A2    = (const float*)d_in[13];
    const float* ab2   = (const float*)d_in[14];
    const float* A3    = (const float*)d_in[15];
    const float* ab3   = (const float*)d_in[16];
    float* out = (float*)d_out;

    frag_w1_kernel<<<128, 256>>>(W1);
    frag_kernel<<<64, 256>>>(W2, A1, A2);
    se_kernel<<<NN, 128>>>(nodes, u2e, A1, ab1);

    mma_table_kernel<<<TU_CTAS + TA_CTAS + 2, 256>>>(u2e, ua2e, r2e);

    cudaFuncSetAttribute(agg_mma_kernel,
                         cudaFuncAttributeMaxDynamicSharedMemorySize, SMEM_BYTES);
    agg_mma_kernel<<<NN, 256, SMEM_BYTES>>>(prel, pnbr, attrs,
                                            b1, b2, ab2, A3, ab3, out);
}

// round 9
// speedup vs baseline: 1.3853x; 1.3853x over previous
#include <cuda_runtime.h>
#include <math.h>
#include <stdint.h>

// Problem constants
#define NN 4096
#define NU_ 100000
#define NR_ 32
#define NA_ 5000

// ---------------- device global scratch (allocation-free) ----------------
__device__ float g_Tu[(size_t)NU_ * 256];   // u2e @ W1[256:384]
__device__ float g_Ta[(size_t)NA_ * 256];   // ua2e @ W1[384:512]
__device__ float g_Tr1[NR_ * 256];          // r2e @ W1[0:128]
__device__ float g_Tr2[NR_ * 256];          // r2e @ W1[128:256]
__device__ float g_se[NN * 128];            // u2e[nodes] @ A1[128:256] + ab1
// W2 fragments: PRE-SPLIT tf32 hi/lo float4 {bh0,bh1,bl0,bl1} (R5 format, best agg)
__device__ float4 g_W2f[32 * 16 * 32];      // W2 [256x128]: [ks8][nt16][lane]
// A1/A2 fragments: RAW fp32 float2 {b0,b1} (single-pass tf32 consumers)
__device__ float2 g_A1f[16 * 16 * 32];      // A1[0:128][128]
__device__ float2 g_A2f[16 * 16 * 32];      // A2 [128x128]
// W1 fragments: RAW fp32 float2, ntot=32 (R6 format, best table)
__device__ float2 g_W1f[4 * 16 * 32 * 32];  // W1 [512x256]: [p][ks8][nt32][lane]

// ---------------- helpers ----------------
__device__ __forceinline__ float tf32_hif(float x) {
    return __int_as_float(__float_as_int(x) & 0xffffe000);
}
__device__ __forceinline__ uint32_t tf32_bits(float x) {
    return __float_as_uint(x) & 0xffffe000u;
}
__device__ __forceinline__ void mma8(float c[4],
    uint32_t a0, uint32_t a1, uint32_t a2, uint32_t a3,
    uint32_t b0, uint32_t b1)
{
    asm volatile(
        "mma.sync.aligned.m16n8k8.row.col.f32.tf32.tf32.f32 "
        "{%0,%1,%2,%3}, {%4,%5,%6,%7}, {%8,%9}, {%0,%1,%2,%3};"
        : "+f"(c[0]), "+f"(c[1]), "+f"(c[2]), "+f"(c[3])
        : "r"(a0), "r"(a1), "r"(a2), "r"(a3), "r"(b0), "r"(b1));
}

// 3x-split GEMM with PRE-SPLIT float4 B fragments (R5's best-measured agg path)
template<int NT>
__device__ __forceinline__ void warp_gemm_ps(
    const float* __restrict__ As, int astride, int ksteps,
    const float4* __restrict__ Bf, int ntot, int nt_base,
    int gid, int tid4, int lane, float acc[NT][4])
{
    #pragma unroll
    for (int i = 0; i < NT; i++)
        #pragma unroll
        for (int c = 0; c < 4; c++) acc[i][c] = 0.f;

    for (int ks = 0; ks < ksteps; ks++) {
        const float* a0p = As + gid * astride + ks * 8 + tid4;
        const float* a1p = As + (gid + 8) * astride + ks * 8 + tid4;
        const float x0 = a0p[0], x1 = a1p[0], x2 = a0p[4], x3 = a1p[4];
        const uint32_t ah0 = tf32_bits(x0), ah1 = tf32_bits(x1);
        const uint32_t ah2 = tf32_bits(x2), ah3 = tf32_bits(x3);
        const uint32_t al0 = tf32_bits(x0 - __uint_as_float(ah0));
        const uint32_t al1 = tf32_bits(x1 - __uint_as_float(ah1));
        const uint32_t al2 = tf32_bits(x2 - __uint_as_float(ah2));
        const uint32_t al3 = tf32_bits(x3 - __uint_as_float(ah3));
        const float4* bp = Bf + (ks * ntot + nt_base) * 32 + lane;
        #pragma unroll
        for (int nt = 0; nt < NT; nt++) {
            const float4 b = __ldg(bp + nt * 32);
            const uint32_t bh0 = __float_as_uint(b.x), bh1 = __float_as_uint(b.y);
            const uint32_t bl0 = __float_as_uint(b.z), bl1 = __float_as_uint(b.w);
            mma8(acc[nt], ah0, ah1, ah2, ah3, bh0, bh1);
            mma8(acc[nt], ah0, ah1, ah2, ah3, bl0, bl1);
            mma8(acc[nt], al0, al1, al2, al3, bh0, bh1);
        }
    }
}

// 3x-split GEMM with RAW float2 B fragments, split in regs (R6's best table path)
template<int NT>
__device__ __forceinline__ void warp_gemm_raw3(
    const float* __restrict__ As, int astride, int ksteps,
    const float2* __restrict__ Bf, int ntot, int nt_base,
    int gid, int tid4, int lane, float acc[NT][4])
{
    #pragma unroll
    for (int i = 0; i < NT; i++)
        #pragma unroll
        for (int c = 0; c < 4; c++) acc[i][c] = 0.f;

    for (int ks = 0; ks < ksteps; ks++) {
        const float* a0p = As + gid * astride + ks * 8 + tid4;
        const float* a1p = As + (gid + 8) * astride + ks * 8 + tid4;
        const float x0 = a0p[0], x1 = a1p[0], x2 = a0p[4], x3 = a1p[4];
        const uint32_t ah0 = tf32_bits(x0), ah1 = tf32_bits(x1);
        const uint32_t ah2 = tf32_bits(x2), ah3 = tf32_bits(x3);
        const uint32_t al0 = tf32_bits(x0 - __uint_as_float(ah0));
        const uint32_t al1 = tf32_bits(x1 - __uint_as_float(ah1));
        const uint32_t al2 = tf32_bits(x2 - __uint_as_float(ah2));
        const uint32_t al3 = tf32_bits(x3 - __uint_as_float(ah3));
        const float2* bp = Bf + (ks * ntot + nt_base) * 32 + lane;
        #pragma unroll
        for (int nt = 0; nt < NT; nt++) {
            const float2 b = __ldg(bp + nt * 32);
            const uint32_t bh0 = tf32_bits(b.x), bh1 = tf32_bits(b.y);
            const uint32_t bl0 = tf32_bits(b.x - __uint_as_float(bh0));
            const uint32_t bl1 = tf32_bits(b.y - __uint_as_float(bh1));
            mma8(acc[nt], ah0, ah1, ah2, ah3, bh0, bh1);
            mma8(acc[nt], ah0, ah1, ah2, ah3, bl0, bl1);
            mma8(acc[nt], al0, al1, al2, al3, bh0, bh1);
        }
    }
}

// SINGLE-pass tf32 GEMM (attention path: errors damped ~64x by near-uniform softmax)
template<int NT>
__device__ __forceinline__ void warp_gemm_1x(
    const float* __restrict__ As, int astride, int ksteps,
    const float2* __restrict__ Bf, int ntot, int nt_base,
    int gid, int tid4, int lane, float acc[NT][4])
{
    #pragma unroll
    for (int i = 0; i < NT; i++)
        #pragma unroll
        for (int c = 0; c < 4; c++) acc[i][c] = 0.f;

    for (int ks = 0; ks < ksteps; ks++) {
        const float* a0p = As + gid * astride + ks * 8 + tid4;
        const float* a1p = As + (gid + 8) * astride + ks * 8 + tid4;
        const uint32_t ah0 = tf32_bits(a0p[0]), ah1 = tf32_bits(a1p[0]);
        const uint32_t ah2 = tf32_bits(a0p[4]), ah3 = tf32_bits(a1p[4]);
        const float2* bp = Bf + (ks * ntot + nt_base) * 32 + lane;
        #pragma unroll
        for (int nt = 0; nt < NT; nt++) {
            const float2 b = __ldg(bp + nt * 32);
            mma8(acc[nt], ah0, ah1, ah2, ah3, tf32_bits(b.x), tf32_bits(b.y));
        }
    }
}

// ---------------- SMEM layout for agg (float indices), 1 node/CTA ----------------
#define OFF_B1   0      // 256
#define OFF_B2   256    // 128
#define OFF_SE   384    // 128
#define OFF_AB2  512    // 128
#define OFF_A3   640    // 128
#define OFF_LGP  768    // 128
#define OFF_LG   896    // 64
#define OFF_REL  960    // 128 ints
#define OFF_NBR  1088   // 64 ints
#define OFF_ATT  1152   // 512 ints
#define OFF_H1   1664   // 64 x 260
#define OFF_H    18304  // 64 x 132
#define H1S      260
#define HS       132
#define SMEM_FLOATS 26752
#define SMEM_BYTES  (SMEM_FLOATS * 4)   // 107008

// ---------------- Fragment builders ----------------
// b0 = B[k0+(lane&3)][n0+(lane>>2)], b1 = B[k0+(lane&3)+4][n], B row-major [K][N=128].
// W2 -> pre-split float4; A1/A2 -> raw float2.
__global__ __launch_bounds__(256) void frag_kernel(
    const float* __restrict__ W2, const float* __restrict__ A1,
    const float* __restrict__ A2)
{
    int idx = blockIdx.x * 256 + threadIdx.x;   // 32768 total
    if (idx < 16384) {                          // W2: pre-split
        const int j = idx;
        const int ks = j >> 9;
        const int nt = (j >> 5) & 15;
        const int lane = j & 31;
        const int k = ks * 8 + (lane & 3);
        const int n = nt * 8 + (lane >> 2);
        const float x0 = W2[k * 128 + n];
        const float x1 = W2[(k + 4) * 128 + n];
        const float h0 = tf32_hif(x0), h1 = tf32_hif(x1);
        float4 o;
        o.x = h0; o.y = h1;
        o.z = tf32_hif(x0 - h0);
        o.w = tf32_hif(x1 - h1);
        g_W2f[j] = o;
    } else if (idx < 32768) {                   // A1 / A2: raw
        const int which = (idx < 24576) ? 0 : 1;
        const float* W = which ? A2 : A1;
        float2* out = which ? g_A2f : g_A1f;
        const int j = idx - (which ? 24576 : 16384);
        const int ks = j >> 9;
        const int nt = (j >> 5) & 15;
        const int lane = j & 31;
        const int k = ks * 8 + (lane & 3);
        const int n = nt * 8 + (lane >> 2);
        float2 o;
        o.x = W[k * 128 + n];
        o.y = W[(k + 4) * 128 + n];
        out[j] = o;
    }
}

// W1 [512][256] row-major -> 4 parts of [128][256], raw float2, ntot=32.
__global__ __launch_bounds__(256) void frag_w1_kernel(const float* __restrict__ W1)
{
    int idx = blockIdx.x * 256 + threadIdx.x;   // 65536 total
    if (idx >= 65536) return;
    const int p = idx >> 14;
    const int j = idx & 16383;
    const int ks = j >> 10;
    const int nt = (j >> 5) & 31;
    const int lane = j & 31;
    const int k = ks * 8 + (lane & 3);
    const int n = nt * 8 + (lane >> 2);
    float2 o;
    o.x = W1[(p * 128 + k) * 256 + n];
    o.y = W1[(p * 128 + k + 4) * 256 + n];
    g_W1f[p * 16384 + j] = o;
}

// ---------------- se precompute ----------------
__global__ __launch_bounds__(128) void se_kernel(
    const int* __restrict__ nodes, const float* __restrict__ u2e,
    const float* __restrict__ A1, const float* __restrict__ ab1)
{
    const int n = blockIdx.x;
    const int d = threadIdx.x;
    __shared__ float s[128];
    s[d] = u2e[(size_t)nodes[n] * 128 + d];
    __syncthreads();
    float acc = ab1[d];
    #pragma unroll 4
    for (int i = 0; i < 128; i++) acc = fmaf(s[i], A1[(128 + i) * 128 + d], acc);
    g_se[n * 128 + d] = acc;
}

// ---------------- Unified tensor-core table kernel (R6's proven 151us shape) ----------------
#define TU_CTAS 1563
#define TA_CTAS 79
__global__ __launch_bounds__(256) void mma_table_kernel(
    const float* __restrict__ u2e, const float* __restrict__ ua2e,
    const float* __restrict__ r2e)
{
    __shared__ float s_a[64 * 132];
    const int b = blockIdx.x;
    const int t = threadIdx.x;

    const float* emb; float* out; const float2* Bf; int rows; int row0;
    if (b < TU_CTAS)                 { emb = u2e;  out = g_Tu;  Bf = g_W1f + 2 * 16384; rows = NU_; row0 = b * 64; }
    else if (b < TU_CTAS + TA_CTAS)  { emb = ua2e; out = g_Ta;  Bf = g_W1f + 3 * 16384; rows = NA_; row0 = (b - TU_CTAS) * 64; }
    else if (b == TU_CTAS + TA_CTAS) { emb = r2e;  out = g_Tr1; Bf = g_W1f;             rows = NR_; row0 = 0; }
    else                             { emb = r2e;  out = g_Tr2; Bf = g_W1f + 1 * 16384; rows = NR_; row0 = 0; }

    for (int i = t; i < 64 * 32; i += 256) {
        const int r = i >> 5, c4 = i & 31;
        float4 v = make_float4(0.f, 0.f, 0.f, 0.f);
        if (row0 + r < rows)
            v = *(const float4*)(emb + (size_t)(row0 + r) * 128 + c4 * 4);
        *(float4*)(s_a + r * 132 + c4 * 4) = v;
    }
    __syncthreads();

    const int w = t >> 5, lane = t & 31;
    const int gid = lane >> 2, tid4 = lane & 3;
    const int rt = w & 3;
    const int ch = w >> 2;
    const int nt_base = ch * 16;

    float acc[16][4];
    warp_gemm_raw3<16>(s_a + rt * 16 * 132, 132, 16, Bf, 32, nt_base,
                       gid, tid4, lane, acc);

    const int r0 = rt * 16 + gid;
    #pragma unroll
    for (int nt = 0; nt < 16; nt++) {
        const int col = (nt_base + nt) * 8 + 2 * tid4;
        if (row0 + r0 < rows) {
            float2 v; v.x = acc[nt][0]; v.y = acc[nt][1];
            *(float2*)(out + (size_t)(row0 + r0) * 256 + col) = v;
        }
        if (row0 + r0 + 8 < rows) {
            float2 v; v.x = acc[nt][2]; v.y = acc[nt][3];
            *(float2*)(out + (size_t)(row0 + r0 + 8) * 256 + col) = v;
        }
    }
}

// ---------------- agg epilogue helper ----------------
__device__ __forceinline__ void warp_epilogue(
    const float acc[8][4], const float* __restrict__ bias,
    float* __restrict__ dst, int dstride, int rt, int nt_base, int gid, int tid4)
{
    const int row0 = rt * 16 + gid;
    #pragma unroll
    for (int nt = 0; nt < 8; nt++) {
        const int col = (nt_base + nt) * 8 + 2 * tid4;
        const float b0 = bias[col], b1 = bias[col + 1];
        float2 v0, v1;
        v0.x = fmaxf(acc[nt][0] + b0, 0.f);
        v0.y = fmaxf(acc[nt][1] + b1, 0.f);
        v1.x = fmaxf(acc[nt][2] + b0, 0.f);
        v1.y = fmaxf(acc[nt][3] + b1, 0.f);
        *(float2*)(dst + row0 * dstride + col) = v0;
        *(float2*)(dst + (row0 + 8) * dstride + col) = v1;
    }
}

// ---------------- Fused kernel: one CTA = one node (64 paths), 256 thr ----------------
__global__ __launch_bounds__(256, 2) void agg_mma_kernel(
    const int* __restrict__ prel, const int* __restrict__ pnbr,
    const int* __restrict__ attrs,
    const float* __restrict__ b1, const float* __restrict__ b2,
    const float* __restrict__ ab2, const float* __restrict__ A3,
    const float* __restrict__ ab3, float* __restrict__ out)
{
    extern __shared__ float sm[];
    const int n = blockIdx.x;
    const int t = threadIdx.x;
    const int w = t >> 5, lane = t & 31;
    const int gid = lane >> 2, tid4 = lane & 3;
    const int rt = w & 3;
    const int ch = w >> 2;
    const int nt_base = ch * 8;

    int* s_rel = (int*)(sm + OFF_REL);
    int* s_nbr = (int*)(sm + OFF_NBR);
    int* s_att = (int*)(sm + OFF_ATT);

    sm[OFF_B1 + t] = b1[t];
    if (t < 128) {
        sm[OFF_B2 + t] = b2[t];
        sm[OFF_SE + t] = g_se[n * 128 + t];
        sm[OFF_AB2 + t] = ab2[t];
        sm[OFF_A3 + t] = A3[t];
        s_rel[t] = prel[n * 128 + t];
    }
    if (t < 64) s_nbr[t] = pnbr[n * 64 + t];
    for (int i = t; i < 512; i += 256) s_att[i] = attrs[n * 512 + i];
    __syncthreads();

    // ---- gather: h1[k][0:256] = relu(b1 + Tr1 + Tr2 + Tu + sum_a Ta) ----
    {
        float* s_h1 = sm + OFF_H1;
        const int ks = t >> 6;
        const int jj = t & 63;
        for (int kb = 0; kb < 16; kb++) {
            const int k = kb * 4 + ks;
            const int r0 = s_rel[2 * k], r1 = s_rel[2 * k + 1], nb = s_nbr[k];
            float4 acc = *(const float4*)(sm + OFF_B1 + jj * 4);
            float4 v;
            v = ((const float4*)(g_Tr1 + r0 * 256))[jj];
            acc.x += v.x; acc.y += v.y; acc.z += v.z; acc.w += v.w;
            v = ((const float4*)(g_Tr2 + r1 * 256))[jj];
            acc.x += v.x; acc.y += v.y; acc.z += v.z; acc.w += v.w;
            v = ((const float4*)(g_Tu + (size_t)nb * 256))[jj];
            acc.x += v.x; acc.y += v.y; acc.z += v.z; acc.w += v.w;
            #pragma unroll
            for (int a = 0; a < 8; a++) {
                v = ((const float4*)(g_Ta + (size_t)s_att[k * 8 + a] * 256))[jj];
                acc.x += v.x; acc.y += v.y; acc.z += v.z; acc.w += v.w;
            }
            acc.x = fmaxf(acc.x, 0.f); acc.y = fmaxf(acc.y, 0.f);
            acc.z = fmaxf(acc.z, 0.f); acc.w = fmaxf(acc.w, 0.f);
            ((float4*)(s_h1 + k * H1S))[jj] = acc;
        }
    }
    __syncthreads();

    float acc[8][4];

    // ---- GEMM1: h = relu(h1 @ W2 + b2)  — 3x split (feeds output directly) ----
    warp_gemm_ps<8>(sm + OFF_H1 + rt * 16 * H1S, H1S, 32, g_W2f, 16, nt_base,
                    gid, tid4, lane, acc);
    warp_epilogue(acc, sm + OFF_B2, sm + OFF_H, HS, rt, nt_base, gid, tid4);
    __syncthreads();

    // ---- GEMM2: a1 = relu(h @ A1[0:128] + se)  — single tf32 (attention path) ----
    warp_gemm_1x<8>(sm + OFF_H + rt * 16 * HS, HS, 16, g_A1f, 16, nt_base,
                    gid, tid4, lane, acc);
    warp_epilogue(acc, sm + OFF_SE, sm + OFF_H1, HS, rt, nt_base, gid, tid4);
    __syncthreads();

    // ---- GEMM3: a2 = relu(a1 @ A2 + ab2); logits fused — single tf32 ----
    warp_gemm_1x<8>(sm + OFF_H1 + rt * 16 * HS, HS, 16, g_A2f, 16, nt_base,
                    gid, tid4, lane, acc);
    {
        float p0 = 0.f, p1 = 0.f;
        #pragma unroll
        for (int nt = 0; nt < 8; nt++) {
            const int col = (nt_base + nt) * 8 + 2 * tid4;
            const float b0 = sm[OFF_AB2 + col], b1v = sm[OFF_AB2 + col + 1];
            const float w0 = sm[OFF_A3 + col], w1 = sm[OFF_A3 + col + 1];
            p0 = fmaf(fmaxf(acc[nt][0] + b0, 0.f), w0, p0);
            p0 = fmaf(fmaxf(acc[nt][1] + b1v, 0.f), w1, p0);
            p1 = fmaf(fmaxf(acc[nt][2] + b0, 0.f), w0, p1);
            p1 = fmaf(fmaxf(acc[nt][3] + b1v, 0.f), w1, p1);
        }
        p0 += __shfl_xor_sync(0xffffffffu, p0, 1);
        p0 += __shfl_xor_sync(0xffffffffu, p0, 2);
        p1 += __shfl_xor_sync(0xffffffffu, p1, 1);
        p1 += __shfl_xor_sync(0xffffffffu, p1, 2);
        if (tid4 == 0) {
            sm[OFF_LGP + ch * 64 + rt * 16 + gid] = p0;
            sm[OFF_LGP + ch * 64 + rt * 16 + gid + 8] = p1;
        }
    }
    __syncthreads();

    // ---- softmax over 64 logits (warp 0) ----
    if (t < 32) {
        const float a3b = ab3[0];
        float l0 = a3b + sm[OFF_LGP + t] + sm[OFF_LGP + 64 + t];
        float l1 = a3b + sm[OFF_LGP + t + 32] + sm[OFF_LGP + 96 + t];
        float m = fmaxf(l0, l1);
        #pragma unroll
        for (int off = 16; off; off >>= 1)
            m = fmaxf(m, __shfl_xor_sync(0xffffffffu, m, off));
        float e0 = expf(l0 - m), e1 = expf(l1 - m);
        float s = e0 + e1;
        #pragma unroll
        for (int off = 16; off; off >>= 1)
            s += __shfl_xor_sync(0xffffffffu, s, off);
        const float inv = 1.f / s;
        sm[OFF_LG + t] = e0 * inv;
        sm[OFF_LG + t + 32] = e1 * inv;
    }
    __syncthreads();

    // ---- out[n][d] = sum_k w[k] * h[k][d] ----
    if (t < 128) {
        const float* hb = sm + OFF_H;
        float acc2 = 0.f;
        #pragma unroll 4
        for (int k = 0; k < 64; k++)
            acc2 = fmaf(sm[OFF_LG + k], hb[k * HS + t], acc2);
        out[(size_t)n * 128 + t] = acc2;
    }
}

// -------------------------------------------------------------------------
extern "C" void kernel_launch(void* const* d_in, const int* in_sizes, int n_in,
                              void* d_out, int out_size)
{
    const int*   nodes = (const int*)d_in[0];
    const int*   prel  = (const int*)d_in[1];
    const int*   pnbr  = (const int*)d_in[2];
    const int*   attrs = (const int*)d_in[3];
    const float* u2e   = (const float*)d_in[4];
    const float* r2e   = (const float*)d_in[5];
    const float* ua2e  = (const float*)d_in[6];
    const float* W1    = (const float*)d_in[7];
    const float* b1    = (const float*)d_in[8];
    const float* W2    = (const float*)d_in[9];
    const float* b2    = (const float*)d_in[10];
    const float* A1    = (const float*)d_in[11];
    const float* ab1   = (const float*)d_in[12];
    const float* A2    = (const float*)d_in[13];
    const float* ab2   = (const float*)d_in[14];
    const float* A3    = (const float*)d_in[15];
    const float* ab3   = (const float*)d_in[16];
    float* out = (float*)d_out;

    frag_w1_kernel<<<256, 256>>>(W1);
    frag_kernel<<<128, 256>>>(W2, A1, A2);
    se_kernel<<<NN, 128>>>(nodes, u2e, A1, ab1);

    mma_table_kernel<<<TU_CTAS + TA_CTAS + 2, 256>>>(u2e, ua2e, r2e);

    cudaFuncSetAttribute(agg_mma_kernel,
                         cudaFuncAttributeMaxDynamicSharedMemorySize, SMEM_BYTES);
    agg_mma_kernel<<<NN, 256, SMEM_BYTES>>>(prel, pnbr, attrs,
                                            b1, b2, ab2, A3, ab3, out);
}

// round 11
// speedup vs baseline: 1.4079x; 1.0164x over previous
#include <cuda_runtime.h>
#include <math.h>
#include <stdint.h>

// Problem constants
#define NN 4096
#define NU_ 100000
#define NR_ 32
#define NA_ 5000

// ---------------- device global scratch (allocation-free) ----------------
__device__ float g_Tu[(size_t)NU_ * 256];   // u2e @ W1[256:384]
__device__ float g_Ta[(size_t)NA_ * 256];   // ua2e @ W1[384:512]
__device__ float g_Tr1[NR_ * 256];          // r2e @ W1[0:128]
__device__ float g_Tr2[NR_ * 256];          // r2e @ W1[128:256]
__device__ float g_se[NN * 128];            // u2e[nodes] @ A1[128:256] + ab1
// W2 fragments: PRE-SPLIT tf32 hi/lo float4 {bh0,bh1,bl0,bl1}
__device__ float4 g_W2f[32 * 16 * 32];      // W2 [256x128]: [ks8][nt16][lane]
// A1/A2 fragments: RAW fp32 float2 {b0,b1} (single-pass tf32 consumers)
__device__ float2 g_A1f[16 * 16 * 32];      // A1[0:128][128]
__device__ float2 g_A2f[16 * 16 * 32];      // A2 [128x128]
// W1 fragments: RAW fp32 float2, ntot=32
__device__ float2 g_W1f[4 * 16 * 32 * 32];  // W1 [512x256]: [p][ks8][nt32][lane]

// ---------------- helpers ----------------
__device__ __forceinline__ float tf32_hif(float x) {
    return __int_as_float(__float_as_int(x) & 0xffffe000);
}
__device__ __forceinline__ uint32_t tf32_bits(float x) {
    return __float_as_uint(x) & 0xffffe000u;
}
__device__ __forceinline__ void mma8(float c[4],
    uint32_t a0, uint32_t a1, uint32_t a2, uint32_t a3,
    uint32_t b0, uint32_t b1)
{
    asm volatile(
        "mma.sync.aligned.m16n8k8.row.col.f32.tf32.tf32.f32 "
        "{%0,%1,%2,%3}, {%4,%5,%6,%7}, {%8,%9}, {%0,%1,%2,%3};"
        : "+f"(c[0]), "+f"(c[1]), "+f"(c[2]), "+f"(c[3])
        : "r"(a0), "r"(a1), "r"(a2), "r"(a3), "r"(b0), "r"(b1));
}

// 3x-split GEMM, PRE-SPLIT float4 B. Compile-time KSTEPS + unroll so ptxas
// software-pipelines B loads across iterations (raise MLP, hide L2 latency).
template<int NT, int KSTEPS>
__device__ __forceinline__ void warp_gemm_ps(
    const float* __restrict__ As, int astride,
    const float4* __restrict__ Bf, int ntot, int nt_base,
    int gid, int tid4, int lane, float acc[NT][4])
{
    #pragma unroll
    for (int i = 0; i < NT; i++)
        #pragma unroll
        for (int c = 0; c < 4; c++) acc[i][c] = 0.f;

    #pragma unroll 4
    for (int ks = 0; ks < KSTEPS; ks++) {
        const float* a0p = As + gid * astride + ks * 8 + tid4;
        const float* a1p = As + (gid + 8) * astride + ks * 8 + tid4;
        const float x0 = a0p[0], x1 = a1p[0], x2 = a0p[4], x3 = a1p[4];
        const uint32_t ah0 = tf32_bits(x0), ah1 = tf32_bits(x1);
        const uint32_t ah2 = tf32_bits(x2), ah3 = tf32_bits(x3);
        const uint32_t al0 = tf32_bits(x0 - __uint_as_float(ah0));
        const uint32_t al1 = tf32_bits(x1 - __uint_as_float(ah1));
        const uint32_t al2 = tf32_bits(x2 - __uint_as_float(ah2));
        const uint32_t al3 = tf32_bits(x3 - __uint_as_float(ah3));
        const float4* bp = Bf + (ks * ntot + nt_base) * 32 + lane;
        #pragma unroll
        for (int nt = 0; nt < NT; nt++) {
            const float4 b = __ldg(bp + nt * 32);
            const uint32_t bh0 = __float_as_uint(b.x), bh1 = __float_as_uint(b.y);
            const uint32_t bl0 = __float_as_uint(b.z), bl1 = __float_as_uint(b.w);
            mma8(acc[nt], ah0, ah1, ah2, ah3, bh0, bh1);
            mma8(acc[nt], ah0, ah1, ah2, ah3, bl0, bl1);
            mma8(acc[nt], al0, al1, al2, al3, bh0, bh1);
        }
    }
}

// 3x-split GEMM, RAW float2 B split in regs (table kernel path).
template<int NT, int KSTEPS>
__device__ __forceinline__ void warp_gemm_raw3(
    const float* __restrict__ As, int astride,
    const float2* __restrict__ Bf, int ntot, int nt_base,
    int gid, int tid4, int lane, float acc[NT][4])
{
    #pragma unroll
    for (int i = 0; i < NT; i++)
        #pragma unroll
        for (int c = 0; c < 4; c++) acc[i][c] = 0.f;

    #pragma unroll 4
    for (int ks = 0; ks < KSTEPS; ks++) {
        const float* a0p = As + gid * astride + ks * 8 + tid4;
        const float* a1p = As + (gid + 8) * astride + ks * 8 + tid4;
        const float x0 = a0p[0], x1 = a1p[0], x2 = a0p[4], x3 = a1p[4];
        const uint32_t ah0 = tf32_bits(x0), ah1 = tf32_bits(x1);
        const uint32_t ah2 = tf32_bits(x2), ah3 = tf32_bits(x3);
        const uint32_t al0 = tf32_bits(x0 - __uint_as_float(ah0));
        const uint32_t al1 = tf32_bits(x1 - __uint_as_float(ah1));
        const uint32_t al2 = tf32_bits(x2 - __uint_as_float(ah2));
        const uint32_t al3 = tf32_bits(x3 - __uint_as_float(ah3));
        const float2* bp = Bf + (ks * ntot + nt_base) * 32 + lane;
        #pragma unroll
        for (int nt = 0; nt < NT; nt++) {
            const float2 b = __ldg(bp + nt * 32);
            const uint32_t bh0 = tf32_bits(b.x), bh1 = tf32_bits(b.y);
            const uint32_t bl0 = tf32_bits(b.x - __uint_as_float(bh0));
            const uint32_t bl1 = tf32_bits(b.y - __uint_as_float(bh1));
            mma8(acc[nt], ah0, ah1, ah2, ah3, bh0, bh1);
            mma8(acc[nt], ah0, ah1, ah2, ah3, bl0, bl1);
            mma8(acc[nt], al0, al1, al2, al3, bh0, bh1);
        }
    }
}

// SINGLE-pass tf32 GEMM (attention path only — R9-validated).
template<int NT, int KSTEPS>
__device__ __forceinline__ void warp_gemm_1x(
    const float* __restrict__ As, int astride,
    const float2* __restrict__ Bf, int ntot, int nt_base,
    int gid, int tid4, int lane, float acc[NT][4])
{
    #pragma unroll
    for (int i = 0; i < NT; i++)
        #pragma unroll
        for (int c = 0; c < 4; c++) acc[i][c] = 0.f;

    #pragma unroll 4
    for (int ks = 0; ks < KSTEPS; ks++) {
        const float* a0p = As + gid * astride + ks * 8 + tid4;
        const float* a1p = As + (gid + 8) * astride + ks * 8 + tid4;
        const uint32_t ah0 = tf32_bits(a0p[0]), ah1 = tf32_bits(a1p[0]);
        const uint32_t ah2 = tf32_bits(a0p[4]), ah3 = tf32_bits(a1p[4]);
        const float2* bp = Bf + (ks * ntot + nt_base) * 32 + lane;
        #pragma unroll
        for (int nt = 0; nt < NT; nt++) {
            const float2 b = __ldg(bp + nt * 32);
            mma8(acc[nt], ah0, ah1, ah2, ah3, tf32_bits(b.x), tf32_bits(b.y));
        }
    }
}

// ---------------- SMEM layout for agg (float indices), 1 node/CTA ----------------
#define OFF_B1   0      // 256
#define OFF_B2   256    // 128
#define OFF_SE   384    // 128
#define OFF_AB2  512    // 128
#define OFF_A3   640    // 128
#define OFF_LGP  768    // 128
#define OFF_LG   896    // 64
#define OFF_REL  960    // 128 ints
#define OFF_NBR  1088   // 64 ints
#define OFF_ATT  1152   // 512 ints
#define OFF_H1   1664   // 64 x 260
#define OFF_H    18304  // 64 x 132
#define H1S      260
#define HS       132
#define SMEM_FLOATS 26752
#define SMEM_BYTES  (SMEM_FLOATS * 4)   // 107008

// ---------------- Fragment builders ----------------
__global__ __launch_bounds__(256) void frag_kernel(
    const float* __restrict__ W2, const float* __restrict__ A1,
    const float* __restrict__ A2)
{
    int idx = blockIdx.x * 256 + threadIdx.x;   // 32768 total
    if (idx < 16384) {                          // W2: pre-split float4
        const int j = idx;
        const int ks = j >> 9;
        const int nt = (j >> 5) & 15;
        const int lane = j & 31;
        const int k = ks * 8 + (lane & 3);
        const int n = nt * 8 + (lane >> 2);
        const float x0 = W2[k * 128 + n];
        const float x1 = W2[(k + 4) * 128 + n];
        const float h0 = tf32_hif(x0), h1 = tf32_hif(x1);
        float4 o;
        o.x = h0; o.y = h1;
        o.z = tf32_hif(x0 - h0);
        o.w = tf32_hif(x1 - h1);
        g_W2f[j] = o;
    } else if (idx < 32768) {                   // A1 / A2: raw float2
        const int which = (idx < 24576) ? 0 : 1;
        const float* W = which ? A2 : A1;
        float2* out = which ? g_A2f : g_A1f;
        const int j = idx - (which ? 24576 : 16384);
        const int ks = j >> 9;
        const int nt = (j >> 5) & 15;
        const int lane = j & 31;
        const int k = ks * 8 + (lane & 3);
        const int n = nt * 8 + (lane >> 2);
        float2 o;
        o.x = W[k * 128 + n];
        o.y = W[(k + 4) * 128 + n];
        out[j] = o;
    }
}

__global__ __launch_bounds__(256) void frag_w1_kernel(const float* __restrict__ W1)
{
    int idx = blockIdx.x * 256 + threadIdx.x;   // 65536 total
    if (idx >= 65536) return;
    const int p = idx >> 14;
    const int j = idx & 16383;
    const int ks = j >> 10;
    const int nt = (j >> 5) & 31;
    const int lane = j & 31;
    const int k = ks * 8 + (lane & 3);
    const int n = nt * 8 + (lane >> 2);
    float2 o;
    o.x = W1[(p * 128 + k) * 256 + n];
    o.y = W1[(p * 128 + k + 4) * 256 + n];
    g_W1f[p * 16384 + j] = o;
}

// ---------------- se precompute (exact fp32) ----------------
__global__ __launch_bounds__(128) void se_kernel(
    const int* __restrict__ nodes, const float* __restrict__ u2e,
    const float* __restrict__ A1, const float* __restrict__ ab1)
{
    const int n = blockIdx.x;
    const int d = threadIdx.x;
    __shared__ float s[128];
    s[d] = u2e[(size_t)nodes[n] * 128 + d];
    __syncthreads();
    float acc = ab1[d];
    #pragma unroll 4
    for (int i = 0; i < 128; i++) acc = fmaf(s[i], A1[(128 + i) * 128 + d], acc);
    g_se[n * 128 + d] = acc;
}

// ---------------- Unified tensor-core table kernel (64 rows/CTA) ----------------
#define TU_CTAS 1563
#define TA_CTAS 79
__global__ __launch_bounds__(256) void mma_table_kernel(
    const float* __restrict__ u2e, const float* __restrict__ ua2e,
    const float* __restrict__ r2e)
{
    __shared__ float s_a[64 * 132];
    const int b = blockIdx.x;
    const int t = threadIdx.x;

    const float* emb; float* out; const float2* Bf; int rows; int row0;
    if (b < TU_CTAS)                 { emb = u2e;  out = g_Tu;  Bf = g_W1f + 2 * 16384; rows = NU_; row0 = b * 64; }
    else if (b < TU_CTAS + TA_CTAS)  { emb = ua2e; out = g_Ta;  Bf = g_W1f + 3 * 16384; rows = NA_; row0 = (b - TU_CTAS) * 64; }
    else if (b == TU_CTAS + TA_CTAS) { emb = r2e;  out = g_Tr1; Bf = g_W1f;             rows = NR_; row0 = 0; }
    else                             { emb = r2e;  out = g_Tr2; Bf = g_W1f + 1 * 16384; rows = NR_; row0 = 0; }

    for (int i = t; i < 64 * 32; i += 256) {
        const int r = i >> 5, c4 = i & 31;
        float4 v = make_float4(0.f, 0.f, 0.f, 0.f);
        if (row0 + r < rows)
            v = *(const float4*)(emb + (size_t)(row0 + r) * 128 + c4 * 4);
        *(float4*)(s_a + r * 132 + c4 * 4) = v;
    }
    __syncthreads();

    const int w = t >> 5, lane = t & 31;
    const int gid = lane >> 2, tid4 = lane & 3;
    const int rt = w & 3;
    const int ch = w >> 2;
    const int nt_base = ch * 16;

    float acc[16][4];
    warp_gemm_raw3<16, 16>(s_a + rt * 16 * 132, 132, Bf, 32, nt_base,
                           gid, tid4, lane, acc);

    const int r0 = rt * 16 + gid;
    #pragma unroll
    for (int nt = 0; nt < 16; nt++) {
        const int col = (nt_base + nt) * 8 + 2 * tid4;
        if (row0 + r0 < rows) {
            float2 v; v.x = acc[nt][0]; v.y = acc[nt][1];
            *(float2*)(out + (size_t)(row0 + r0) * 256 + col) = v;
        }
        if (row0 + r0 + 8 < rows) {
            float2 v; v.x = acc[nt][2]; v.y = acc[nt][3];
            *(float2*)(out + (size_t)(row0 + r0 + 8) * 256 + col) = v;
        }
    }
}

// ---------------- agg epilogue helper ----------------
__device__ __forceinline__ void warp_epilogue(
    const float acc[8][4], const float* __restrict__ bias,
    float* __restrict__ dst, int dstride, int rt, int nt_base, int gid, int tid4)
{
    const int row0 = rt * 16 + gid;
    #pragma unroll
    for (int nt = 0; nt < 8; nt++) {
        const int col = (nt_base + nt) * 8 + 2 * tid4;
        const float b0 = bias[col], b1 = bias[col + 1];
        float2 v0, v1;
        v0.x = fmaxf(acc[nt][0] + b0, 0.f);
        v0.y = fmaxf(acc[nt][1] + b1, 0.f);
        v1.x = fmaxf(acc[nt][2] + b0, 0.f);
        v1.y = fmaxf(acc[nt][3] + b1, 0.f);
        *(float2*)(dst + row0 * dstride + col) = v0;
        *(float2*)(dst + (row0 + 8) * dstride + col) = v1;
    }
}

// ---------------- Fused kernel: one CTA = one node (64 paths), 256 thr ----------------
__global__ __launch_bounds__(256, 2) void agg_mma_kernel(
    const int* __restrict__ prel, const int* __restrict__ pnbr,
    const int* __restrict__ attrs,
    const float* __restrict__ b1, const float* __restrict__ b2,
    const float* __restrict__ ab2, const float* __restrict__ A3,
    const float* __restrict__ ab3, float* __restrict__ out)
{
    extern __shared__ float sm[];
    const int n = blockIdx.x;
    const int t = threadIdx.x;
    const int w = t >> 5, lane = t & 31;
    const int gid = lane >> 2, tid4 = lane & 3;
    const int rt = w & 3;
    const int ch = w >> 2;
    const int nt_base = ch * 8;

    int* s_rel = (int*)(sm + OFF_REL);
    int* s_nbr = (int*)(sm + OFF_NBR);
    int* s_att = (int*)(sm + OFF_ATT);

    sm[OFF_B1 + t] = b1[t];
    if (t < 128) {
        sm[OFF_B2 + t] = b2[t];
        sm[OFF_SE + t] = g_se[n * 128 + t];
        sm[OFF_AB2 + t] = ab2[t];
        sm[OFF_A3 + t] = A3[t];
        s_rel[t] = prel[n * 128 + t];
    }
    if (t < 64) s_nbr[t] = pnbr[n * 64 + t];
    for (int i = t; i < 512; i += 256) s_att[i] = attrs[n * 512 + i];
    __syncthreads();

    // ---- gather: h1[k][0:256] = relu(b1 + Tr1 + Tr2 + Tu + sum_a Ta) ----
    {
        float* s_h1 = sm + OFF_H1;
        const int ks = t >> 6;
        const int jj = t & 63;
        for (int kb = 0; kb < 16; kb++) {
            const int k = kb * 4 + ks;
            const int r0 = s_rel[2 * k], r1 = s_rel[2 * k + 1], nb = s_nbr[k];
            float4 acc = *(const float4*)(sm + OFF_B1 + jj * 4);
            float4 v;
            v = ((const float4*)(g_Tr1 + r0 * 256))[jj];
            acc.x += v.x; acc.y += v.y; acc.z += v.z; acc.w += v.w;
            v = ((const float4*)(g_Tr2 + r1 * 256))[jj];
            acc.x += v.x; acc.y += v.y; acc.z += v.z; acc.w += v.w;
            v = ((const float4*)(g_Tu + (size_t)nb * 256))[jj];
            acc.x += v.x; acc.y += v.y; acc.z += v.z; acc.w += v.w;
            #pragma unroll
            for (int a = 0; a < 8; a++) {
                v = ((const float4*)(g_Ta + (size_t)s_att[k * 8 + a] * 256))[jj];
                acc.x += v.x; acc.y += v.y; acc.z += v.z; acc.w += v.w;
            }
            acc.x = fmaxf(acc.x, 0.f); acc.y = fmaxf(acc.y, 0.f);
            acc.z = fmaxf(acc.z, 0.f); acc.w = fmaxf(acc.w, 0.f);
            ((float4*)(s_h1 + k * H1S))[jj] = acc;
        }
    }
    __syncthreads();

    float acc[8][4];

    // ---- GEMM1: h = relu(h1 @ W2 + b2) — 3x split (direct output path) ----
    warp_gemm_ps<8, 32>(sm + OFF_H1 + rt * 16 * H1S, H1S, g_W2f, 16, nt_base,
                        gid, tid4, lane, acc);
    warp_epilogue(acc, sm + OFF_B2, sm + OFF_H, HS, rt, nt_base, gid, tid4);
    __syncthreads();

    // ---- GEMM2: a1 = relu(h @ A1[0:128] + se) — single tf32 (softmax-damped) ----
    warp_gemm_1x<8, 16>(sm + OFF_H + rt * 16 * HS, HS, g_A1f, 16, nt_base,
                        gid, tid4, lane, acc);
    warp_epilogue(acc, sm + OFF_SE, sm + OFF_H1, HS, rt, nt_base, gid, tid4);
    __syncthreads();

    // ---- GEMM3: a2 = relu(a1 @ A2 + ab2); logits fused — single tf32 ----
    warp_gemm_1x<8, 16>(sm + OFF_H1 + rt * 16 * HS, HS, g_A2f, 16, nt_base,
                        gid, tid4, lane, acc);
    {
        float p0 = 0.f, p1 = 0.f;
        #pragma unroll
        for (int nt = 0; nt < 8; nt++) {
            const int col = (nt_base + nt) * 8 + 2 * tid4;
            const float b0 = sm[OFF_AB2 + col], b1v = sm[OFF_AB2 + col + 1];
            const float w0 = sm[OFF_A3 + col], w1 = sm[OFF_A3 + col + 1];
            p0 = fmaf(fmaxf(acc[nt][0] + b0, 0.f), w0, p0);
            p0 = fmaf(fmaxf(acc[nt][1] + b1v, 0.f), w1, p0);
            p1 = fmaf(fmaxf(acc[nt][2] + b0, 0.f), w0, p1);
            p1 = fmaf(fmaxf(acc[nt][3] + b1v, 0.f), w1, p1);
        }
        p0 += __shfl_xor_sync(0xffffffffu, p0, 1);
        p0 += __shfl_xor_sync(0xffffffffu, p0, 2);
        p1 += __shfl_xor_sync(0xffffffffu, p1, 1);
        p1 += __shfl_xor_sync(0xffffffffu, p1, 2);
        if (tid4 == 0) {
            sm[OFF_LGP + ch * 64 + rt * 16 + gid] = p0;
            sm[OFF_LGP + ch * 64 + rt * 16 + gid + 8] = p1;
        }
    }
    __syncthreads();

    // ---- softmax over 64 logits (warp 0) ----
    if (t < 32) {
        const float a3b = ab3[0];
        float l0 = a3b + sm[OFF_LGP + t] + sm[OFF_LGP + 64 + t];
        float l1 = a3b + sm[OFF_LGP + t + 32] + sm[OFF_LGP + 96 + t];
        float m = fmaxf(l0, l1);
        #pragma unroll
        for (int off = 16; off; off >>= 1)
            m = fmaxf(m, __shfl_xor_sync(0xffffffffu, m, off));
        float e0 = expf(l0 - m), e1 = expf(l1 - m);
        float s = e0 + e1;
        #pragma unroll
        for (int off = 16; off; off >>= 1)
            s += __shfl_xor_sync(0xffffffffu, s, off);
        const float inv = 1.f / s;
        sm[OFF_LG + t] = e0 * inv;
        sm[OFF_LG + t + 32] = e1 * inv;
    }
    __syncthreads();

    // ---- out[n][d] = sum_k w[k] * h[k][d] ----
    if (t < 128) {
        const float* hb = sm + OFF_H;
        float acc2 = 0.f;
        #pragma unroll 4
        for (int k = 0; k < 64; k++)
            acc2 = fmaf(sm[OFF_LG + k], hb[k * HS + t], acc2);
        out[(size_t)n * 128 + t] = acc2;
    }
}

// -------------------------------------------------------------------------
extern "C" void kernel_launch(void* const* d_in, const int* in_sizes, int n_in,
                              void* d_out, int out_size)
{
    const int*   nodes = (const int*)d_in[0];
    const int*   prel  = (const int*)d_in[1];
    const int*   pnbr  = (const int*)d_in[2];
    const int*   attrs = (const int*)d_in[3];
    const float* u2e   = (const float*)d_in[4];
    const float* r2e   = (const float*)d_in[5];
    const float* ua2e  = (const float*)d_in[6];
    const float* W1    = (const float*)d_in[7];
    const float* b1    = (const float*)d_in[8];
    const float* W2    = (const float*)d_in[9];
    const float* b2    = (const float*)d_in[10];
    const float* A1    = (const float*)d_in[11];
    const float* ab1   = (const float*)d_in[12];
    const float* A2    = (const float*)d_in[13];
    const float* ab2   = (const float*)d_in[14];
    const float* A3    = (const float*)d_in[15];
    const float* ab3   = (const float*)d_in[16];
    float* out = (float*)d_out;

    frag_w1_kernel<<<256, 256>>>(W1);
    frag_kernel<<<128, 256>>>(W2, A1, A2);
    se_kernel<<<NN, 128>>>(nodes, u2e, A1, ab1);

    mma_table_kernel<<<TU_CTAS + TA_CTAS + 2, 256>>>(u2e, ua2e, r2e);

    cudaFuncSetAttribute(agg_mma_kernel,
                         cudaFuncAttributeMaxDynamicSharedMemorySize, SMEM_BYTES);
    agg_mma_kernel<<<NN, 256, SMEM_BYTES>>>(prel, pnbr, attrs,
                                            b1, b2, ab2, A3, ab3, out);
}